// round 15
// baseline (speedup 1.0000x reference)
#include <cuda_runtime.h>
#include <cuda_bf16.h>
#include <math.h>
#include <stdint.h>

// Problem constants
#define BB   128
#define DD   256
#define SS   512
#define KK   50
#define HH   256
#define NROW 65536           // B*S
#define OUT_PRED   0         // 256 floats
#define OUT_ZERO   256
#define OUT_CSIM   257
#define OUT_CFAR   258
#define OUT_TPNN   259       // 3,276,800 floats (ODD offset: scalar stores only!)
#define OUT_AE     3277059

// -------- scratch (static device memory; no allocations allowed) --------
__device__ float g_tvn[DD * KK];                 // normalized topic vectors [d][k]
__device__ float g_tvnT[DD * 56];                // tvn^T tf32-rounded, padded
__device__ float g_W2c[HH * 2];                  // rec2 @ Wc (256 x 2)
__device__ float g_rnorm[NROW];                  // 1/max(||x||,1e-12) per row
__device__ float g_aepartA[512];                 // per-kernelA-CTA sum of ||xn||^2
__device__ float g_corr[NROW];                   // per-row ae correction (flagged only)
__device__ float g_hsum[BB * HH];                // sum_s relu(nn@rec1) per batch
__device__ float g_topsum[KK];                   // per-concept top-32 sums
__device__ int   g_nzcnt;                        // flagged-row count
__device__ int   g_nzlist[NROW];                 // flagged rows
__device__ int   g_hist[KK * 128];               // tpn histogram
__device__ int   g_candcnt[KK];                  // candidate counts (bin >= 12)
__device__ float g_cand[(size_t)KK * NROW];      // candidate values

// ---------------- tf32 helpers ----------------
__device__ __forceinline__ uint32_t tf32cvt(float x) {
    uint32_t r;
    asm("cvt.rna.tf32.f32 %0, %1;" : "=r"(r) : "f"(x));
    return r;
}
__device__ __forceinline__ void mma_tf32(float* c, uint32_t a0, uint32_t a1,
                                         uint32_t a2, uint32_t a3,
                                         uint32_t b0, uint32_t b1) {
    asm volatile(
        "mma.sync.aligned.m16n8k8.row.col.f32.tf32.tf32.f32 "
        "{%0,%1,%2,%3},{%4,%5,%6,%7},{%8,%9},{%0,%1,%2,%3};"
        : "+f"(c[0]), "+f"(c[1]), "+f"(c[2]), "+f"(c[3])
        : "r"(a0), "r"(a1), "r"(a2), "r"(a3), "r"(b0), "r"(b1));
}

// ===== prepZero: all per-launch scratch zeroing =========================
__global__ void prepZero() {
    int t = threadIdx.x, b = blockIdx.x;
    if (b < 128) {
        g_hsum[b * 256 + t] = 0.f;
    } else {
        for (int i = t; i < KK * 128; i += 256) g_hist[i] = 0;
        if (t < KK) g_candcnt[t] = 0;
        if (t == 0) g_nzcnt = 0;
    }
}

// ===== prepTv: tv_n + concept_far + tvnT ================================
__global__ void prepTv(const float* __restrict__ tv, float* __restrict__ out) {
    __shared__ float cpart[KK * 5];
    __shared__ float cinv[64];
    __shared__ float sd[DD];
    int t = threadIdx.x;
    if (t < KK * 5) {
        int k = t / 5, p = t - k * 5;
        float s = 0.f;
        for (int d = p; d < DD; d += 5) { float v = tv[d * KK + k]; s += v * v; }
        cpart[t] = s;
    }
    __syncthreads();
    if (t < KK) {
        float s = cpart[t * 5] + cpart[t * 5 + 1] + cpart[t * 5 + 2]
                + cpart[t * 5 + 3] + cpart[t * 5 + 4];
        cinv[t] = 1.0f / fmaxf(sqrtf(s), 1e-12f);
    }
    __syncthreads();
    {   // thread t == d
        float sum = 0.f;
        for (int k = 0; k < KK; k++) {
            float v = tv[t * KK + k] * cinv[k];
            g_tvn[t * KK + k] = v;
            g_tvnT[t * 56 + k] = __uint_as_float(tf32cvt(v));
            sum += v;
        }
        for (int k = KK; k < 56; k++) g_tvnT[t * 56 + k] = 0.f;
        sd[t] = sum;
    }
    __syncthreads();
    if (t == 0) {
        float g = 0.f;
        for (int d = 0; d < DD; d++) g += sd[d] * sd[d];
        out[OUT_CFAR] = (g - (float)KK) / (float)(KK * KK);
        out[OUT_ZERO] = 0.0f;
    }
}

// ===== prepW2c: W2c = rec2 @ Wc (256 x 2) ===============================
__global__ void prepW2c(const float* __restrict__ rec2, const float* __restrict__ Wc) {
    int h = threadIdx.x;
    float w0 = 0.f, w1 = 0.f;
    #pragma unroll 8
    for (int d = 0; d < DD; d++) {
        float r = rec2[h * DD + d];
        w0 = fmaf(r, Wc[d * 2], w0);
        w1 = fmaf(r, Wc[d * 2 + 1], w1);
    }
    g_W2c[h * 2] = w0;
    g_W2c[h * 2 + 1] = w1;
}

// =================== kernelA: tf32 mma topic path (no tpnT stores) ======
#define XS_STR  261
#define TVN_STR 56
#define CBUF_W  56
#define A_SMEM_F (128 * XS_STR + 256 * TVN_STR + 128 + 8 + 512 + 128 + KK * 128 + KK * CBUF_W + 64)
#define A_SMEM_BYTES (A_SMEM_F * 4)

__global__ void __launch_bounds__(512) kernelA(const float* __restrict__ fin,
                                               float* __restrict__ out) {
    extern __shared__ float sm[];
    float* xs   = sm;                         // [128][261]
    float* tvs  = xs + 128 * XS_STR;          // [256][56]
    float* rn   = tvs + 256 * TVN_STR;        // 128
    float* red8 = rn + 128;                   // 8
    float* ssqp = red8 + 8;                   // 512 (layout keep)
    float* flg  = ssqp + 512;                 // 128
    int*   hloc = (int*)(flg + 128);          // [50][128]; first also ssq scratch
    float* cbuf = (float*)(hloc + KK * 128);  // [50][56]
    int*   ccnt = (int*)(cbuf + KK * CBUF_W); // [50] (+pad)

    int t = threadIdx.x;
    int cid = blockIdx.x;
    int b = cid >> 2, st = cid & 3;
    int s0 = st * 128;
    int row0 = cid * 128;
    const float* fb = fin + (size_t)b * DD * SS + s0;

    for (int i = t; i < 256 * TVN_STR; i += 512) tvs[i] = g_tvnT[i];
    if (t < 128) flg[t] = 0.f;
    if (t < KK) ccnt[t] = 0;

    // x load: float4 along s (warp w owns d = w + 16*i); ssq -> hloc scratch
    {
        int w = t >> 5, l = t & 31;
        float ssq4[4] = {0.f, 0.f, 0.f, 0.f};
        #pragma unroll 4
        for (int i = 0; i < 16; i++) {
            int d = w + 16 * i;
            float4 v = *(const float4*)(fb + (size_t)d * SS + l * 4);
            ssq4[0] = fmaf(v.x, v.x, ssq4[0]);
            ssq4[1] = fmaf(v.y, v.y, ssq4[1]);
            ssq4[2] = fmaf(v.z, v.z, ssq4[2]);
            ssq4[3] = fmaf(v.w, v.w, ssq4[3]);
            xs[(l * 4 + 0) * XS_STR + d] = __uint_as_float(tf32cvt(v.x));
            xs[(l * 4 + 1) * XS_STR + d] = __uint_as_float(tf32cvt(v.y));
            xs[(l * 4 + 2) * XS_STR + d] = __uint_as_float(tf32cvt(v.z));
            xs[(l * 4 + 3) * XS_STR + d] = __uint_as_float(tf32cvt(v.w));
        }
        float* sw = (float*)hloc;            // [128][17]
        #pragma unroll
        for (int c = 0; c < 4; c++) sw[(l * 4 + c) * 17 + w] = ssq4[c];
    }
    __syncthreads();

    // row norms (exact fp32) + ae base term
    if (t < 128) {
        float* sw = (float*)hloc;
        float s = 0.f;
        #pragma unroll
        for (int i = 0; i < 16; i++) s += sw[t * 17 + i];
        float r = 1.0f / fmaxf(sqrtf(s), 1e-12f);
        rn[t] = r;
        g_rnorm[row0 + t] = r;
        float xn2 = s * r * r;
        #pragma unroll
        for (int off = 16; off >= 1; off >>= 1)
            xn2 += __shfl_xor_sync(0xffffffffu, xn2, off);
        if ((t & 31) == 0) red8[t >> 5] = xn2;
    }
    __syncthreads();
    if (t == 0) g_aepartA[cid] = red8[0] + red8[1] + red8[2] + red8[3];
    // zero hloc (ssq scratch consumed)
    for (int i = t; i < KK * 128; i += 512) hloc[i] = 0;

    // tf32 mma GEMM, d-split across warp halves
    int warp = t >> 5, lane = t & 31, g = lane >> 2, tid = lane & 3;
    int j0 = (warp & 7) * 16;
    int dbase = (warp >> 3) * 128;
    float acc[7][4];
    #pragma unroll
    for (int nt = 0; nt < 7; nt++)
        #pragma unroll
        for (int c = 0; c < 4; c++) acc[nt][c] = 0.f;

    const uint32_t* xsu = (const uint32_t*)xs;
    const uint32_t* tvu = (const uint32_t*)tvs;
    #pragma unroll 2
    for (int dd = 0; dd < 128; dd += 8) {
        int d0 = dbase + dd;
        uint32_t a0 = xsu[(j0 + g) * XS_STR + d0 + tid];
        uint32_t a1 = xsu[(j0 + 8 + g) * XS_STR + d0 + tid];
        uint32_t a2 = xsu[(j0 + g) * XS_STR + d0 + tid + 4];
        uint32_t a3 = xsu[(j0 + 8 + g) * XS_STR + d0 + tid + 4];
        #pragma unroll
        for (int nt = 0; nt < 7; nt++) {
            uint32_t b0 = tvu[(d0 + tid) * TVN_STR + nt * 8 + g];
            uint32_t b1 = tvu[(d0 + tid + 4) * TVN_STR + nt * 8 + g];
            mma_tf32(acc[nt], a0, a1, a2, a3, b0, b1);
        }
    }
    __syncthreads();                 // all xs reads done
    float* scratch = xs;             // reuse as [128][56] partial buffer
    if (warp >= 8) {
        #pragma unroll
        for (int nt = 0; nt < 7; nt++)
            #pragma unroll
            for (int c = 0; c < 4; c++) {
                int jj = j0 + g + ((c >= 2) ? 8 : 0);
                int k = nt * 8 + tid * 2 + (c & 1);
                scratch[jj * 56 + k] = acc[nt][c];
            }
    }
    __syncthreads();
    if (warp < 8) {
        #pragma unroll
        for (int nt = 0; nt < 7; nt++) {
            #pragma unroll
            for (int c = 0; c < 4; c++) {
                int jj = j0 + g + ((c >= 2) ? 8 : 0);
                int k = nt * 8 + tid * 2 + (c & 1);
                float full = acc[nt][c] + scratch[jj * 56 + k];
                if (k < KK) {
                    float tpn = full * rn[jj];
                    int bin = (int)(tpn * 128.0f);
                    if (bin >= 8) atomicAdd(&hloc[k * 128 + min(bin, 127)], 1);
                    if (bin >= 12) {                              // candidate
                        int ci = atomicAdd(&ccnt[k], 1);
                        if (ci < CBUF_W) cbuf[k * CBUF_W + ci] = tpn;
                        else {                                    // rare spill
                            int gi = atomicAdd(&g_candcnt[k], 1);
                            g_cand[(size_t)k * NROW + gi] = tpn;
                        }
                    }
                    if (tpn > 0.2985f) flg[jj] = 1.f;  // 1.5e-3 tf32 margin
                }
            }
        }
    }
    __syncthreads();
    if (t < 128 && flg[t] != 0.f) {
        int idx = atomicAdd(&g_nzcnt, 1);
        g_nzlist[idx] = row0 + t;
    }
    // bulk candidate flush: one atomic per concept
    if (t < KK) {
        int cnt = min(ccnt[t], CBUF_W);
        if (cnt > 0) {
            int base = atomicAdd(&g_candcnt[t], cnt);
            for (int i = 0; i < cnt; i++)
                g_cand[(size_t)t * NROW + base + i] = cbuf[t * CBUF_W + i];
        }
    }
    // tpnn zeros for all rows (flagged rows overwritten exactly by kernelRC)
    {
        float* tpnn = out + OUT_TPNN + (size_t)row0 * KK;
        for (int i = t; i < 128 * KK; i += 512) tpnn[i] = 0.f;
    }
    // flush histogram
    for (int i = t; i < KK * 128; i += 512) {
        int c = hloc[i];
        if (c) atomicAdd(&g_hist[i], c);
    }
}

// ===== kernelRC: blocks 0-127 exact sparse rows; 128-177 top-32 sums =====
__global__ void __launch_bounds__(256) kernelRC(const float* __restrict__ fin,
                                                const float* __restrict__ rec1,
                                                const float* __restrict__ rec2,
                                                float* __restrict__ out) {
    __shared__ float xrow[DD];
    __shared__ float msk[KK];
    __shared__ float nn[KK];
    __shared__ float r1[HH];
    __shared__ float red[256];
    __shared__ float inv_s;
    __shared__ int   hcnt[120];
    __shared__ int   s_bstar, scnt, sovf;
    __shared__ float svals[2048];
    __shared__ int   rarg[256];

    int t = threadIdx.x;
    if (blockIdx.x < 128) {
        // ---------------- kernelR: flagged rows, EXACT fp32 -------------
        int cnt = g_nzcnt;
        float* tpnn_out = out + OUT_TPNN;
        for (int i = blockIdx.x; i < cnt; i += 128) {
            int row = g_nzlist[i];
            int b = row >> 9, s = row & 511;
            float r = g_rnorm[row];
            xrow[t] = fin[(size_t)b * DD * SS + (size_t)t * SS + s];
            __syncthreads();
            if (t < KK) {
                float tp = 0.f;
                #pragma unroll 8
                for (int d = 0; d < DD; d++) tp += xrow[d] * g_tvn[d * KK + t];
                msk[t] = ((tp * r) > 0.3f) ? tp : 0.f;   // EXACT mask decision
            }
            __syncthreads();
            if (t == 0) {
                float su = 0.f;
                for (int k = 0; k < KK; k++) su += msk[k];
                inv_s = 1.0f / (su + 0.001f + 1e-8f);
            }
            __syncthreads();
            if (t < KK) {
                float v = msk[t] * inv_s;
                nn[t] = v;
                tpnn_out[(size_t)row * KK + t] = v;      // exact tpnn
            }
            __syncthreads();
            float z = 0.f;
            #pragma unroll 5
            for (int k = 0; k < KK; k++) z += nn[k] * rec1[k * HH + t];
            z = fmaxf(z, 0.f);
            r1[t] = z;
            atomicAdd(&g_hsum[b * HH + t], z);
            __syncthreads();
            float o = 0.f;
            #pragma unroll 8
            for (int h = 0; h < HH; h++) o += r1[h] * rec2[h * DD + t];
            float xn = xrow[t] * r;
            red[t] = o * o - 2.0f * xn * o;
            __syncthreads();
            for (int off = 128; off > 0; off >>= 1) {
                if (t < off) red[t] += red[t + off];
                __syncthreads();
            }
            if (t == 0) g_corr[row] = red[0];
            __syncthreads();
        }
        return;
    }

    // ---------------- finalC: bstar + candidate filter + top-32 ---------
    int k = blockIdx.x - 128;
    if (t < 120) hcnt[t] = g_hist[k * 128 + 8 + t];
    if (t == 0) { scnt = 0; sovf = 0; }
    __syncthreads();
    if (t == 0) {
        int cum = 0, bstar = 7;
        for (int b = 127; b >= 8; b--) {
            cum += hcnt[b - 8];
            if (cum >= 32) { bstar = b; break; }
        }
        s_bstar = bstar;
    }
    __syncthreads();
    int bstar = s_bstar;
    int thr = bstar - 1;
    bool fast = (bstar != 7) && (thr >= 12);

    if (fast) {
        int C = g_candcnt[k];
        for (int i = t; i < C; i += 256) {
            float v = g_cand[(size_t)k * NROW + i];
            if ((int)(v * 128.0f) >= thr) {
                int idx = atomicAdd(&scnt, 1);
                if (idx < 2048) svals[idx] = v;
                else sovf = 1;
            }
        }
    }
    __syncthreads();
    if (fast && !sovf) {
        // counting-rank: sum values with rank < 32 (fully parallel)
        int C = scnt;
        float part = 0.f;
        for (int i = t; i < C; i += 256) {
            float v = svals[i];
            int rank = 0;
            for (int j = 0; j < C; j++) {
                float u = svals[j];
                rank += (u > v || (u == v && j < i)) ? 1 : 0;
            }
            if (rank < 32) part += v;
        }
        red[t] = part;
        __syncthreads();
        for (int off = 128; off > 0; off >>= 1) {
            if (t < off) red[t] += red[t + off];
            __syncthreads();
        }
        if (t == 0) g_topsum[k] = red[0];
    } else {
        // pathological fallback (adversarial data only): recompute tpn for
        // this concept from inputs, collect to g_cand, then select.
        __shared__ int fcnt;
        if (t == 0) fcnt = 0;
        __syncthreads();
        for (int i = t; i < NROW; i += 256) {
            int bb = i >> 9, ssv = i & 511;
            float tp = 0.f;
            for (int d = 0; d < DD; d++)
                tp += fin[(size_t)bb * DD * SS + (size_t)d * SS + ssv] * g_tvn[d * KK + k];
            float tpn = tp * g_rnorm[i];
            int bin = (int)(tpn * 128.0f);
            if (bstar == 7 || bin >= thr) {
                int idx = atomicAdd(&fcnt, 1);
                g_cand[(size_t)k * NROW + idx] = tpn;
            }
        }
        __syncthreads();
        int C2 = fcnt;
        float* src = g_cand + (size_t)k * NROW;
        float sum = 0.f;
        int rounds = C2 < 32 ? C2 : 32;
        for (int r = 0; r < rounds; r++) {
            float m = -1e30f; int mi = -1;
            for (int i = t; i < C2; i += 256) {
                float x = src[i];
                if (x > m) { m = x; mi = i; }
            }
            red[t] = m; rarg[t] = mi;
            __syncthreads();
            for (int off = 128; off > 0; off >>= 1) {
                if (t < off && red[t + off] > red[t]) {
                    red[t] = red[t + off]; rarg[t] = rarg[t + off];
                }
                __syncthreads();
            }
            if (t == 0) { sum += red[0]; src[rarg[0]] = -1e30f; }
            __syncthreads();
        }
        if (t == 0) g_topsum[k] = sum;
    }
}

// ===== kernelPF: blocks 0-127 pred via W2c; block 128 ae + csim =========
__global__ void __launch_bounds__(256) kernelPF(const float* __restrict__ bc,
                                                float* __restrict__ out) {
    __shared__ float r0[256], r1[256];
    int t = threadIdx.x;
    if (blockIdx.x < 128) {
        int b = blockIdx.x;
        float hs = g_hsum[b * HH + t];       // coalesced row load
        r0[t] = hs * g_W2c[t * 2];
        r1[t] = hs * g_W2c[t * 2 + 1];
        __syncthreads();
        for (int off = 128; off > 0; off >>= 1) {
            if (t < off) { r0[t] += r0[t + off]; r1[t] += r1[t + off]; }
            __syncthreads();
        }
        if (t == 0) {
            out[b * 2 + 0] = r0[0] * (1.0f / 512.0f) + bc[0];
            out[b * 2 + 1] = r1[0] * (1.0f / 512.0f) + bc[1];
        }
        return;
    }
    // block 128: ae + csim
    int cnt = g_nzcnt;
    float s = 0.f;
    for (int i = t; i < cnt; i += 256) s += g_corr[g_nzlist[i]];
    for (int i = t; i < 512; i += 256) s += g_aepartA[i];
    r0[t] = s;
    __syncthreads();
    for (int off = 128; off > 0; off >>= 1) {
        if (t < off) r0[t] += r0[t + off];
        __syncthreads();
    }
    if (t == 0) {
        out[OUT_AE] = r0[0] / 16777216.0f;
        float cs = 0.f;
        for (int k = 0; k < KK; k++) cs += g_topsum[k];
        out[OUT_CSIM] = -cs / 1600.0f;
    }
}

// ============================ launcher ===================================
extern "C" void kernel_launch(void* const* d_in, const int* in_sizes, int n_in,
                              void* d_out, int out_size) {
    const float* f_input      = (const float*)d_in[0];
    const float* topic_vector = (const float*)d_in[2];
    const float* rec1         = (const float*)d_in[3];
    const float* rec2         = (const float*)d_in[4];
    const float* Wc           = (const float*)d_in[5];
    const float* bc           = (const float*)d_in[6];
    float* out = (float*)d_out;

    cudaFuncSetAttribute(kernelA, cudaFuncAttributeMaxDynamicSharedMemorySize, A_SMEM_BYTES);

    prepZero<<<129, 256>>>();                                  // idx 0
    prepTv<<<1, 256>>>(topic_vector, out);                     // idx 1
    prepW2c<<<1, 256>>>(rec2, Wc);                             // idx 2
    kernelA<<<512, 512, A_SMEM_BYTES>>>(f_input, out);         // idx 3 -> profiled
    kernelRC<<<178, 256>>>(f_input, rec1, rec2, out);          // idx 4
    kernelPF<<<129, 256>>>(bc, out);                           // idx 5
}

// round 16
// speedup vs baseline: 1.1206x; 1.1206x over previous
#include <cuda_runtime.h>
#include <cuda_bf16.h>
#include <math.h>
#include <stdint.h>

// Problem constants
#define BB   128
#define DD   256
#define SS   512
#define KK   50
#define HH   256
#define NROW 65536           // B*S
#define OUT_PRED   0         // 256 floats
#define OUT_ZERO   256
#define OUT_CSIM   257
#define OUT_CFAR   258
#define OUT_TPNN   259       // 3,276,800 floats (ODD offset: scalar stores only!)
#define OUT_AE     3277059

// -------- scratch (static device memory; no allocations allowed) --------
__device__ float g_tvn[DD * KK];                 // normalized topic vectors [d][k]
__device__ float g_tvnT[DD * 56];                // tvn^T tf32-rounded, padded
__device__ float g_W2c[HH * 2];                  // rec2 @ Wc (256 x 2)
__device__ float g_rnorm[NROW];                  // 1/max(||x||,1e-12) per row
__device__ float g_aepartA[1024];                // per-kernelA-CTA sum of ||xn||^2
__device__ float g_corr[NROW];                   // per-row ae correction (flagged only)
__device__ float g_hsum[BB * HH];                // sum_s relu(nn@rec1) per batch
__device__ float g_topsum[KK];                   // per-concept top-32 sums
__device__ int   g_nzcnt;                        // flagged-row count
__device__ int   g_nzlist[NROW];                 // flagged rows
__device__ int   g_hist[KK * 128];               // tpn histogram
__device__ int   g_candcnt[KK];                  // candidate counts (bin >= 12)
__device__ float g_cand[(size_t)KK * NROW];      // candidate values

// ---------------- tf32 helpers ----------------
__device__ __forceinline__ uint32_t tf32cvt(float x) {
    uint32_t r;
    asm("cvt.rna.tf32.f32 %0, %1;" : "=r"(r) : "f"(x));
    return r;
}
__device__ __forceinline__ void mma_tf32(float* c, uint32_t a0, uint32_t a1,
                                         uint32_t a2, uint32_t a3,
                                         uint32_t b0, uint32_t b1) {
    asm volatile(
        "mma.sync.aligned.m16n8k8.row.col.f32.tf32.tf32.f32 "
        "{%0,%1,%2,%3},{%4,%5,%6,%7},{%8,%9},{%0,%1,%2,%3};"
        : "+f"(c[0]), "+f"(c[1]), "+f"(c[2]), "+f"(c[3])
        : "r"(a0), "r"(a1), "r"(a2), "r"(a3), "r"(b0), "r"(b1));
}

// ===== prepZero: all per-launch scratch zeroing =========================
__global__ void prepZero() {
    int t = threadIdx.x, b = blockIdx.x;
    if (b < 128) {
        g_hsum[b * 256 + t] = 0.f;
    } else {
        for (int i = t; i < KK * 128; i += 256) g_hist[i] = 0;
        if (t < KK) g_candcnt[t] = 0;
        if (t == 0) g_nzcnt = 0;
    }
}

// ===== prepTvW: block 0 tvn/cfar/tvnT; block 1 W2c ======================
__global__ void prepTvW(const float* __restrict__ tv, const float* __restrict__ rec2,
                        const float* __restrict__ Wc, float* __restrict__ out) {
    int t = threadIdx.x;
    if (blockIdx.x == 1) {              // W2c = rec2 @ Wc  (256 x 2)
        int h = t;
        float w0 = 0.f, w1 = 0.f;
        #pragma unroll 8
        for (int d = 0; d < DD; d++) {
            float r = rec2[h * DD + d];
            w0 = fmaf(r, Wc[d * 2], w0);
            w1 = fmaf(r, Wc[d * 2 + 1], w1);
        }
        g_W2c[h * 2] = w0;
        g_W2c[h * 2 + 1] = w1;
        return;
    }
    __shared__ float cpart[KK * 5];
    __shared__ float cinv[64];
    __shared__ float sd[DD];
    if (t < KK * 5) {
        int k = t / 5, p = t - k * 5;
        float s = 0.f;
        for (int d = p; d < DD; d += 5) { float v = tv[d * KK + k]; s += v * v; }
        cpart[t] = s;
    }
    __syncthreads();
    if (t < KK) {
        float s = cpart[t * 5] + cpart[t * 5 + 1] + cpart[t * 5 + 2]
                + cpart[t * 5 + 3] + cpart[t * 5 + 4];
        cinv[t] = 1.0f / fmaxf(sqrtf(s), 1e-12f);
    }
    __syncthreads();
    {   // thread t == d
        float sum = 0.f;
        for (int k = 0; k < KK; k++) {
            float v = tv[t * KK + k] * cinv[k];
            g_tvn[t * KK + k] = v;
            g_tvnT[t * 56 + k] = __uint_as_float(tf32cvt(v));
            sum += v;
        }
        for (int k = KK; k < 56; k++) g_tvnT[t * 56 + k] = 0.f;
        sd[t] = sum;
    }
    __syncthreads();
    if (t == 0) {
        float g = 0.f;
        for (int d = 0; d < DD; d++) g += sd[d] * sd[d];
        out[OUT_CFAR] = (g - (float)KK) / (float)(KK * KK);
        out[OUT_ZERO] = 0.0f;
    }
}

// ======= kernelA: 64-row tiles, 2 CTAs/SM, B fragments from gmem ========
#define XS_STR  261
#define CBW     32
// floats: xs 64*261 | rn 64 | ssqp 64*9 | flg 64 | red8 8 | hist 50*32 |
//         cbuf 50*32 | ccnt 50 | pad
#define A_SMEM_F (64 * XS_STR + 64 + 64 * 9 + 64 + 8 + KK * 32 + KK * CBW + KK + 16)
#define A_SMEM_BYTES (A_SMEM_F * 4)

__global__ void __launch_bounds__(256, 2) kernelA(const float* __restrict__ fin,
                                                  float* __restrict__ out) {
    extern __shared__ float sm[];
    float*    xs     = sm;                            // [64][261]
    float*    rn     = xs + 64 * XS_STR;              // 64
    float*    ssqp   = rn + 64;                       // [64][9]
    float*    flg    = ssqp + 64 * 9;                 // 64
    float*    red8   = flg + 64;                      // 8
    unsigned* hist32 = (unsigned*)(red8 + 8);         // [50][32] packed u8x4
    float*    cbuf   = (float*)(hist32 + KK * 32);    // [50][32]
    int*      ccnt   = (int*)(cbuf + KK * CBW);       // [50]

    int t = threadIdx.x;
    int cid = blockIdx.x;                 // 1024 CTAs
    int b = cid >> 3, st = cid & 7;
    int s0 = st * 64;
    int row0 = cid * 64;
    const float* fb = fin + (size_t)b * DD * SS + s0;

    for (int i = t; i < KK * 32; i += 256) hist32[i] = 0u;
    if (t < 64) flg[t] = 0.f;
    if (t < KK) ccnt[t] = 0;

    // x load: warp w owns d = w + 8*i (32 iters); float2 along s covers 64 rows
    {
        int w = t >> 5, l = t & 31;
        float ss0 = 0.f, ss1 = 0.f;
        #pragma unroll 4
        for (int i = 0; i < 32; i++) {
            int d = w + 8 * i;
            float2 v = *(const float2*)(fb + (size_t)d * SS + l * 2);
            ss0 = fmaf(v.x, v.x, ss0);
            ss1 = fmaf(v.y, v.y, ss1);
            xs[(l * 2 + 0) * XS_STR + d] = __uint_as_float(tf32cvt(v.x));
            xs[(l * 2 + 1) * XS_STR + d] = __uint_as_float(tf32cvt(v.y));
        }
        ssqp[(l * 2 + 0) * 9 + w] = ss0;
        ssqp[(l * 2 + 1) * 9 + w] = ss1;
    }
    __syncthreads();

    // row norms (exact fp32) + ae base term
    if (t < 64) {
        float s = 0.f;
        #pragma unroll
        for (int i = 0; i < 8; i++) s += ssqp[t * 9 + i];
        float r = 1.0f / fmaxf(sqrtf(s), 1e-12f);
        rn[t] = r;
        g_rnorm[row0 + t] = r;
        float xn2 = s * r * r;
        #pragma unroll
        for (int off = 16; off >= 1; off >>= 1)
            xn2 += __shfl_xor_sync(0xffffffffu, xn2, off);
        if ((t & 31) == 0) red8[t >> 5] = xn2;
    }
    __syncthreads();
    if (t == 0) g_aepartA[cid] = red8[0] + red8[1];

    // tf32 mma: 8 warps = 4 m-tiles (16 rows) x 2 d-halves (128 d)
    int warp = t >> 5, lane = t & 31, g = lane >> 2, tid4 = lane & 3;
    int wm = warp & 3, dh = warp >> 2;
    int j0 = wm * 16;
    int dbase = dh * 128;
    float acc[7][4];
    #pragma unroll
    for (int nt = 0; nt < 7; nt++)
        #pragma unroll
        for (int c = 0; c < 4; c++) acc[nt][c] = 0.f;

    const uint32_t* xsu = (const uint32_t*)xs;
    const uint32_t* tvu = (const uint32_t*)g_tvnT;   // GLOBAL (L1-resident 57KB)
    #pragma unroll 2
    for (int dd = 0; dd < 128; dd += 8) {
        int d0 = dbase + dd;
        uint32_t a0 = xsu[(j0 + g) * XS_STR + d0 + tid4];
        uint32_t a1 = xsu[(j0 + 8 + g) * XS_STR + d0 + tid4];
        uint32_t a2 = xsu[(j0 + g) * XS_STR + d0 + tid4 + 4];
        uint32_t a3 = xsu[(j0 + 8 + g) * XS_STR + d0 + tid4 + 4];
        #pragma unroll
        for (int nt = 0; nt < 7; nt++) {
            uint32_t b0 = tvu[(d0 + tid4) * 56 + nt * 8 + g];
            uint32_t b1 = tvu[(d0 + tid4 + 4) * 56 + nt * 8 + g];
            mma_tf32(acc[nt], a0, a1, a2, a3, b0, b1);
        }
    }
    __syncthreads();                 // all xs reads done
    float* scratch = xs;             // reuse as [64][56] partial buffer
    if (dh == 1) {
        #pragma unroll
        for (int nt = 0; nt < 7; nt++)
            #pragma unroll
            for (int c = 0; c < 4; c++) {
                int jj = j0 + g + ((c >= 2) ? 8 : 0);
                int k = nt * 8 + tid4 * 2 + (c & 1);
                scratch[jj * 56 + k] = acc[nt][c];
            }
    }
    __syncthreads();
    if (dh == 0) {
        #pragma unroll
        for (int nt = 0; nt < 7; nt++) {
            #pragma unroll
            for (int c = 0; c < 4; c++) {
                int jj = j0 + g + ((c >= 2) ? 8 : 0);
                int k = nt * 8 + tid4 * 2 + (c & 1);
                float full = acc[nt][c] + scratch[jj * 56 + k];
                if (k < KK) {
                    float tpn = full * rn[jj];
                    int bin = (int)(tpn * 128.0f);
                    if (bin >= 8) {
                        int bc = min(bin, 127);
                        atomicAdd(&hist32[k * 32 + (bc >> 2)], 1u << (8 * (bc & 3)));
                    }
                    if (bin >= 12) {
                        int ci = atomicAdd(&ccnt[k], 1);
                        if (ci < CBW) cbuf[k * CBW + ci] = tpn;
                        else {
                            int gi = atomicAdd(&g_candcnt[k], 1);
                            g_cand[(size_t)k * NROW + gi] = tpn;
                        }
                    }
                    if (tpn > 0.2985f) flg[jj] = 1.f;  // 1.5e-3 tf32 margin
                }
            }
        }
    }
    __syncthreads();
    if (t < 64 && flg[t] != 0.f) {
        int idx = atomicAdd(&g_nzcnt, 1);
        g_nzlist[idx] = row0 + t;
    }
    // bulk candidate flush
    if (t < KK) {
        int cnt = min(ccnt[t], CBW);
        if (cnt > 0) {
            int base = atomicAdd(&g_candcnt[t], cnt);
            for (int i = 0; i < cnt; i++)
                g_cand[(size_t)t * NROW + base + i] = cbuf[t * CBW + i];
        }
    }
    // tpnn zeros for this tile (flagged rows overwritten exactly by kernelRC)
    {
        float* tpnn = out + OUT_TPNN + (size_t)row0 * KK;
        for (int i = t; i < 64 * KK; i += 256) tpnn[i] = 0.f;
    }
    // flush packed histogram
    for (int i = t; i < KK * 32; i += 256) {
        unsigned word = hist32[i];
        if (word) {
            int k = i >> 5, wr = i & 31;
            #pragma unroll
            for (int j = 0; j < 4; j++) {
                int c = (word >> (8 * j)) & 255;
                if (c) atomicAdd(&g_hist[k * 128 + wr * 4 + j], c);
            }
        }
    }
}

// ===== kernelRC: blocks 0-127 exact sparse rows; 128-177 top-32 sums =====
__global__ void __launch_bounds__(256) kernelRC(const float* __restrict__ fin,
                                                const float* __restrict__ rec1,
                                                const float* __restrict__ rec2,
                                                float* __restrict__ out) {
    __shared__ float xrow[DD];
    __shared__ float msk[KK];
    __shared__ float nn[KK];
    __shared__ float r1[HH];
    __shared__ float red[256];
    __shared__ float inv_s;
    __shared__ int   hcnt[120];
    __shared__ int   s_bstar, scnt, sovf;
    __shared__ float svals[2048];
    __shared__ int   rarg[256];

    int t = threadIdx.x;
    if (blockIdx.x < 128) {
        // ---------------- kernelR: flagged rows, EXACT fp32 -------------
        int cnt = g_nzcnt;
        float* tpnn_out = out + OUT_TPNN;
        for (int i = blockIdx.x; i < cnt; i += 128) {
            int row = g_nzlist[i];
            int b = row >> 9, s = row & 511;
            float r = g_rnorm[row];
            xrow[t] = fin[(size_t)b * DD * SS + (size_t)t * SS + s];
            __syncthreads();
            if (t < KK) {
                float tp = 0.f;
                #pragma unroll 8
                for (int d = 0; d < DD; d++) tp += xrow[d] * g_tvn[d * KK + t];
                msk[t] = ((tp * r) > 0.3f) ? tp : 0.f;   // EXACT mask decision
            }
            __syncthreads();
            if (t == 0) {
                float su = 0.f;
                for (int k = 0; k < KK; k++) su += msk[k];
                inv_s = 1.0f / (su + 0.001f + 1e-8f);
            }
            __syncthreads();
            if (t < KK) {
                float v = msk[t] * inv_s;
                nn[t] = v;
                tpnn_out[(size_t)row * KK + t] = v;      // exact tpnn
            }
            __syncthreads();
            float z = 0.f;
            #pragma unroll 5
            for (int k = 0; k < KK; k++) z += nn[k] * rec1[k * HH + t];
            z = fmaxf(z, 0.f);
            r1[t] = z;
            atomicAdd(&g_hsum[b * HH + t], z);
            __syncthreads();
            float o = 0.f;
            #pragma unroll 8
            for (int h = 0; h < HH; h++) o += r1[h] * rec2[h * DD + t];
            float xn = xrow[t] * r;
            red[t] = o * o - 2.0f * xn * o;
            __syncthreads();
            for (int off = 128; off > 0; off >>= 1) {
                if (t < off) red[t] += red[t + off];
                __syncthreads();
            }
            if (t == 0) g_corr[row] = red[0];
            __syncthreads();
        }
        return;
    }

    // ---------------- finalC: bstar + candidate filter + top-32 ---------
    int k = blockIdx.x - 128;
    if (t < 120) hcnt[t] = g_hist[k * 128 + 8 + t];
    if (t == 0) { scnt = 0; sovf = 0; }
    __syncthreads();
    if (t == 0) {
        int cum = 0, bstar = 7;
        for (int b = 127; b >= 8; b--) {
            cum += hcnt[b - 8];
            if (cum >= 32) { bstar = b; break; }
        }
        s_bstar = bstar;
    }
    __syncthreads();
    int bstar = s_bstar;
    int thr = bstar - 1;
    bool fast = (bstar != 7) && (thr >= 12);

    if (fast) {
        int C = g_candcnt[k];
        for (int i = t; i < C; i += 256) {
            float v = g_cand[(size_t)k * NROW + i];
            if ((int)(v * 128.0f) >= thr) {
                int idx = atomicAdd(&scnt, 1);
                if (idx < 2048) svals[idx] = v;
                else sovf = 1;
            }
        }
    }
    __syncthreads();
    if (fast && !sovf) {
        // counting-rank: sum values with rank < 32 (fully parallel)
        int C = scnt;
        float part = 0.f;
        for (int i = t; i < C; i += 256) {
            float v = svals[i];
            int rank = 0;
            for (int j = 0; j < C; j++) {
                float u = svals[j];
                rank += (u > v || (u == v && j < i)) ? 1 : 0;
            }
            if (rank < 32) part += v;
        }
        red[t] = part;
        __syncthreads();
        for (int off = 128; off > 0; off >>= 1) {
            if (t < off) red[t] += red[t + off];
            __syncthreads();
        }
        if (t == 0) g_topsum[k] = red[0];
    } else {
        // pathological fallback (adversarial data only): recompute tpn for
        // this concept from inputs, collect to g_cand, then select.
        __shared__ int fcnt;
        if (t == 0) fcnt = 0;
        __syncthreads();
        for (int i = t; i < NROW; i += 256) {
            int bb = i >> 9, ssv = i & 511;
            float tp = 0.f;
            for (int d = 0; d < DD; d++)
                tp += fin[(size_t)bb * DD * SS + (size_t)d * SS + ssv] * g_tvn[d * KK + k];
            float tpn = tp * g_rnorm[i];
            int bin = (int)(tpn * 128.0f);
            if (bstar == 7 || bin >= thr) {
                int idx = atomicAdd(&fcnt, 1);
                g_cand[(size_t)k * NROW + idx] = tpn;
            }
        }
        __syncthreads();
        int C2 = fcnt;
        float* src = g_cand + (size_t)k * NROW;
        float sum = 0.f;
        int rounds = C2 < 32 ? C2 : 32;
        for (int r = 0; r < rounds; r++) {
            float m = -1e30f; int mi = -1;
            for (int i = t; i < C2; i += 256) {
                float x = src[i];
                if (x > m) { m = x; mi = i; }
            }
            red[t] = m; rarg[t] = mi;
            __syncthreads();
            for (int off = 128; off > 0; off >>= 1) {
                if (t < off && red[t + off] > red[t]) {
                    red[t] = red[t + off]; rarg[t] = rarg[t + off];
                }
                __syncthreads();
            }
            if (t == 0) { sum += red[0]; src[rarg[0]] = -1e30f; }
            __syncthreads();
        }
        if (t == 0) g_topsum[k] = sum;
    }
}

// ===== kernelPF: blocks 0-127 pred via W2c; block 128 ae + csim =========
__global__ void __launch_bounds__(256) kernelPF(const float* __restrict__ bc,
                                                float* __restrict__ out) {
    __shared__ float r0[256], r1[256];
    int t = threadIdx.x;
    if (blockIdx.x < 128) {
        int b = blockIdx.x;
        float hs = g_hsum[b * HH + t];       // coalesced row load
        r0[t] = hs * g_W2c[t * 2];
        r1[t] = hs * g_W2c[t * 2 + 1];
        __syncthreads();
        for (int off = 128; off > 0; off >>= 1) {
            if (t < off) { r0[t] += r0[t + off]; r1[t] += r1[t + off]; }
            __syncthreads();
        }
        if (t == 0) {
            out[b * 2 + 0] = r0[0] * (1.0f / 512.0f) + bc[0];
            out[b * 2 + 1] = r1[0] * (1.0f / 512.0f) + bc[1];
        }
        return;
    }
    // block 128: ae + csim
    int cnt = g_nzcnt;
    float s = 0.f;
    for (int i = t; i < cnt; i += 256) s += g_corr[g_nzlist[i]];
    for (int i = t; i < 1024; i += 256) s += g_aepartA[i];
    r0[t] = s;
    __syncthreads();
    for (int off = 128; off > 0; off >>= 1) {
        if (t < off) r0[t] += r0[t + off];
        __syncthreads();
    }
    if (t == 0) {
        out[OUT_AE] = r0[0] / 16777216.0f;
        float cs = 0.f;
        for (int k = 0; k < KK; k++) cs += g_topsum[k];
        out[OUT_CSIM] = -cs / 1600.0f;
    }
}

// ============================ launcher ===================================
extern "C" void kernel_launch(void* const* d_in, const int* in_sizes, int n_in,
                              void* d_out, int out_size) {
    const float* f_input      = (const float*)d_in[0];
    const float* topic_vector = (const float*)d_in[2];
    const float* rec1         = (const float*)d_in[3];
    const float* rec2         = (const float*)d_in[4];
    const float* Wc           = (const float*)d_in[5];
    const float* bc           = (const float*)d_in[6];
    float* out = (float*)d_out;

    cudaFuncSetAttribute(kernelA, cudaFuncAttributeMaxDynamicSharedMemorySize, A_SMEM_BYTES);

    prepZero<<<129, 256>>>();                                  // idx 0
    prepTvW<<<2, 256>>>(topic_vector, rec2, Wc, out);          // idx 1
    kernelA<<<1024, 256, A_SMEM_BYTES>>>(f_input, out);        // idx 2
    kernelRC<<<178, 256>>>(f_input, rec1, rec2, out);          // idx 3 -> profiled
    kernelPF<<<129, 256>>>(bc, out);                           // idx 4
}